// round 8
// baseline (speedup 1.0000x reference)
#include <cuda_runtime.h>
#include <math.h>
#include <stdint.h>

#define THREADS 128
#define EPS 1e-8f

// bit-reverse of low 3 bits
__device__ __forceinline__ int brev3(int x) {
    return ((x & 1) << 2) | (x & 2) | ((x & 4) >> 2);
}
__device__ __forceinline__ uint64_t pack2(float lo, float hi) {
    uint64_t d; asm("mov.b64 %0, {%1, %2};" : "=l"(d) : "f"(lo), "f"(hi)); return d;
}
__device__ __forceinline__ void unpack2(uint64_t v, float& lo, float& hi) {
    asm("mov.b64 {%0, %1}, %2;" : "=f"(lo), "=f"(hi) : "l"(v));
}
__device__ __forceinline__ uint64_t fma2(uint64_t a, uint64_t b, uint64_t c) {
    uint64_t d; asm("fma.rn.f32x2 %0, %1, %2, %3;" : "=l"(d) : "l"(a), "l"(b), "l"(c)); return d;
}
__device__ __forceinline__ uint64_t mul2(uint64_t a, uint64_t b) {
    uint64_t d; asm("mul.rn.f32x2 %0, %1, %2;" : "=l"(d) : "l"(a), "l"(b)); return d;
}
__device__ __forceinline__ uint64_t add2(uint64_t a, uint64_t b) {
    uint64_t d; asm("add.rn.f32x2 %0, %1, %2;" : "=l"(d) : "l"(a), "l"(b)); return d;
}

__global__ __launch_bounds__(THREADS)
void routing_kernel(const float* __restrict__ caps, float* __restrict__ out) {
    __shared__ float4 part[4][16];
    __shared__ float  zbuf[4];

    const int tid = threadIdx.x;
    const int w = tid >> 5, l = tid & 31;
    const int h = l >> 4, q = l & 15;    // half h owns rows of parity h; lane holds cols 4q..4q+3

    // ---- load 8x float4: row(i) = 16w + 2i + h, cols 4q..4q+3 (512B/warp-instr, coalesced)
    const float4* src = reinterpret_cast<const float4*>(caps) + (size_t)blockIdx.x * 1024
                        + 256 * w + 16 * h + q;
    uint64_t ulo[8], uhi[8];
    #pragma unroll
    for (int i = 0; i < 8; i++) {
        float4 f = src[32 * i];
        ulo[i] = pack2(f.x, f.y);
        uhi[i] = pack2(f.z, f.w);
    }

    float b_mine = 0.0f;                 // logit for row 16w + 2*brev3(q&7) + h (dup at q^8)
    float v0, v1, v2, v3;

    // ================= iter 0: b == 0 -> c uniform = 1/64 =================
    {
        uint64_t a01 = ulo[0], a23 = uhi[0];
        #pragma unroll
        for (int i = 1; i < 8; i++) { a01 = add2(a01, ulo[i]); a23 = add2(a23, uhi[i]); }
        float s0, s1, s2, s3;
        unpack2(a01, s0, s1); unpack2(a23, s2, s3);
        s0 += __shfl_xor_sync(~0u, s0, 16);
        s1 += __shfl_xor_sync(~0u, s1, 16);
        s2 += __shfl_xor_sync(~0u, s2, 16);
        s3 += __shfl_xor_sync(~0u, s3, 16);
        if (h == 0) part[w][q] = make_float4(s0, s1, s2, s3);
        __syncthreads();
        s0 = s1 = s2 = s3 = 0.f;
        #pragma unroll
        for (int ww = 0; ww < 4; ww++) {
            float4 g = part[ww][q];
            s0 += g.x; s1 += g.y; s2 += g.z; s3 += g.w;
        }
        s0 *= (1.f/64.f); s1 *= (1.f/64.f); s2 *= (1.f/64.f); s3 *= (1.f/64.f);
        float t = s0*s0 + s1*s1 + s2*s2 + s3*s3;
        #pragma unroll
        for (int o = 8; o; o >>= 1) t += __shfl_xor_sync(~0u, t, o);
        float scale = t / (1.f + t) / (sqrtf(t) + EPS);
        v0 = scale*s0; v1 = scale*s1; v2 = scale*s2; v3 = scale*s3;
    }

    // ================= iterations 1, 2 =================
    #pragma unroll
    for (int it = 1; it < 3; it++) {
        // ---- agreement partials: p[i] = dot(u[i], v) over lane's 4 cols
        uint64_t v01 = pack2(v0, v1), v23 = pack2(v2, v3);
        float p[8];
        #pragma unroll
        for (int i = 0; i < 8; i++) {
            uint64_t t2 = mul2(ulo[i], v01);
            t2 = fma2(uhi[i], v23, t2);
            float a, b; unpack2(t2, a, b);
            p[i] = a + b;
        }
        // halving butterfly within half (masks 1,2,4), then m=8 exchange-add
        {
            bool up = (q & 1) != 0;
            #pragma unroll
            for (int j = 0; j < 4; j++) {
                float send = up ? p[j] : p[j + 4];
                float keep = up ? p[j + 4] : p[j];
                p[j] = keep + __shfl_xor_sync(~0u, send, 1);
            }
            up = (q & 2) != 0;
            #pragma unroll
            for (int j = 0; j < 2; j++) {
                float send = up ? p[j] : p[j + 2];
                float keep = up ? p[j + 2] : p[j];
                p[j] = keep + __shfl_xor_sync(~0u, send, 2);
            }
            up = (q & 4) != 0;
            {
                float send = up ? p[0] : p[1];
                float keep = up ? p[1] : p[0];
                p[0] = keep + __shfl_xor_sync(~0u, send, 4);
            }
            p[0] += __shfl_xor_sync(~0u, p[0], 8);
        }
        b_mine += p[0];

        // ---- softmax (no max-subtraction: |b| small, fp32-safe). Each row dup x2 -> 0.5 factor
        float e  = __expf(b_mine);
        float Zw = e;
        #pragma unroll
        for (int o = 16; o; o >>= 1) Zw += __shfl_xor_sync(~0u, Zw, o);
        if (l == 0) zbuf[w] = Zw;
        __syncthreads();
        float Z  = 0.5f * (zbuf[0] + zbuf[1] + zbuf[2] + zbuf[3]);
        float cm = e / Z;

        // ---- s-phase: gather c for the 8 same-parity rows, FMA into col accumulators
        uint64_t s01 = 0, s23 = 0;       // bit pattern (0.0f, 0.0f)
        const int srcbase = l & 16;
        #pragma unroll
        for (int j = 0; j < 8; j++) {
            float cr = __shfl_sync(~0u, cm, srcbase + j);   // lane j of this half holds row brev3(j)
            uint64_t cc = pack2(cr, cr);
            int i = brev3(j);
            s01 = fma2(cc, ulo[i], s01);
            s23 = fma2(cc, uhi[i], s23);
        }
        float s0, s1, s2, s3;
        unpack2(s01, s0, s1); unpack2(s23, s2, s3);
        s0 += __shfl_xor_sync(~0u, s0, 16);
        s1 += __shfl_xor_sync(~0u, s1, 16);
        s2 += __shfl_xor_sync(~0u, s2, 16);
        s3 += __shfl_xor_sync(~0u, s3, 16);
        if (h == 0) part[w][q] = make_float4(s0, s1, s2, s3);
        __syncthreads();
        s0 = s1 = s2 = s3 = 0.f;
        #pragma unroll
        for (int ww = 0; ww < 4; ww++) {
            float4 g = part[ww][q];
            s0 += g.x; s1 += g.y; s2 += g.z; s3 += g.w;
        }

        // ---- squash
        float t = s0*s0 + s1*s1 + s2*s2 + s3*s3;
        #pragma unroll
        for (int o = 8; o; o >>= 1) t += __shfl_xor_sync(~0u, t, o);
        float scale = t / (1.f + t) / (sqrtf(t) + EPS);
        v0 = scale*s0; v1 = scale*s1; v2 = scale*s2; v3 = scale*s3;
    }

    // ---- store v: warp 0, half 0: 16 lanes x float4 = 256B coalesced
    if (w == 0 && h == 0) {
        float4* o4 = reinterpret_cast<float4*>(out + (size_t)blockIdx.x * 64);
        o4[q] = make_float4(v0, v1, v2, v3);
    }
}

extern "C" void kernel_launch(void* const* d_in, const int* in_sizes, int n_in,
                              void* d_out, int out_size) {
    const float* caps = (const float*)d_in[0];
    float* out = (float*)d_out;
    int B = in_sizes[0] / (64 * 64);   // 16384
    routing_kernel<<<B, THREADS>>>(caps, out);
}